// round 11
// baseline (speedup 1.0000x reference)
#include <cuda_runtime.h>
#include <cuda_fp16.h>
#include <cstdint>

// ---------------------------------------------------------------------------
// out[b,s,o] = sum_i x[b,s,i] * (nf4[codes][o,i] * scale[o]) + bias[o]
// M = 8192, N = 4096, K = 4096, fp32 in/out.
// Plain sm_103 target (no tcgen05) -> legacy HMMA m16n8k16 pipe.
// R11: warp specialization. 160-thread CTAs: warps 0-3 consume (64x64 warp
// tiles over a 128x128 CTA tile, pure LDSM+MMA), warp 4 produces (all
// cp.async fills, 3-stage ring at distance 3). 2 CTAs/SM.
// ---------------------------------------------------------------------------

static constexpr int M_TOTAL = 8192;
static constexpr int N_TOTAL = 4096;
static constexpr int K_TOTAL = 4096;

static constexpr int BM = 128;
static constexpr int BN = 128;
static constexpr int BK = 64;            // 64 halfs = 128 B/row (SW128)
static constexpr int STAGES = 3;
static constexpr int KITERS = K_TOTAL / BK;  // 64

static constexpr int A_BYTES = BM * 128;                 // 16 KB
static constexpr int B_BYTES = BN * 128;                 // 16 KB
static constexpr int STAGE_BYTES = A_BYTES + B_BYTES;    // 32 KB
static constexpr int SM_STAGE0 = 1024;
static constexpr int SMEM_BYTES = SM_STAGE0 + STAGES * STAGE_BYTES;  // 99328

__device__ __align__(1024) __half g_Wh[(size_t)N_TOTAL * K_TOTAL];  // 32 MB
__device__ __align__(1024) __half g_Xh[(size_t)M_TOTAL * K_TOTAL];  // 64 MB

__constant__ float c_nf4[16] = {
    -1.0f, -0.6961928f, -0.52507305f, -0.3949175f, -0.28444138f, -0.18477343f,
    -0.09105004f, 0.0f, 0.0795803f, 0.1609302f, 0.2461123f, 0.33791524f,
    0.44070983f, 0.562617f, 0.72295684f, 1.0f};

// ------------------------------- helpers -----------------------------------

__device__ __forceinline__ uint32_t smem_u32(const void* p) {
  uint32_t a;
  asm("{ .reg .u64 t; cvta.to.shared.u64 t, %1; cvt.u32.u64 %0, t; }"
      : "=r"(a) : "l"(p));
  return a;
}

#define SWZ128(b) ((b) ^ (((b) >> 3) & 0x70))

#define CP_ASYNC16(dst, gsrc)                                          \
  asm volatile("cp.async.cg.shared.global [%0], [%1], 16;" ::"r"(dst), \
               "l"(gsrc)                                               \
               : "memory")

#define CP_ASYNC_MBAR_ARRIVE(mbar)                                           \
  asm volatile("cp.async.mbarrier.arrive.noinc.shared::cta.b64 [%0];" ::"r"( \
                   (uint32_t)(mbar))                                         \
               : "memory")

#define MBARRIER_INIT(addr, cnt)                                             \
  asm volatile("mbarrier.init.shared.b64 [%0], %1;" ::"r"((uint32_t)(addr)), \
               "r"((uint32_t)(cnt))                                          \
               : "memory")

#define MBARRIER_ARRIVE(addr)                               \
  asm volatile("mbarrier.arrive.shared.b64 _, [%0];" ::"r"( \
                   (uint32_t)(addr))                        \
               : "memory")

#define MBARRIER_WAIT_PARITY(mbar_smem_addr, phase_parity)                     \
  do {                                                                         \
    uint32_t _mbar = (uint32_t)(mbar_smem_addr);                               \
    uint32_t _parity = (uint32_t)(phase_parity);                               \
    uint32_t _done;                                                            \
    asm volatile(                                                              \
        "{\n\t.reg .pred p;\n\t"                                               \
        "mbarrier.try_wait.parity.acquire.cta.shared::cta.b64 p, [%1], %2;\n\t" \
        "selp.b32 %0, 1, 0, p;\n\t}"                                           \
        : "=r"(_done)                                                          \
        : "r"(_mbar), "r"(_parity)                                             \
        : "memory");                                                           \
    if (!_done) {                                                              \
      asm volatile(                                                            \
          "{\n\t.reg .pred P1;\n\t"                                            \
          "WAIT_LOOP_%=:\n\t"                                                  \
          "mbarrier.try_wait.parity.acquire.cta.shared::cta.b64 P1, [%0], %1, 0x989680;\n\t" \
          "@P1 bra.uni WAIT_DONE_%=;\n\t"                                      \
          "bra.uni WAIT_LOOP_%=;\n\t"                                          \
          "WAIT_DONE_%=:\n\t}" ::"r"(_mbar),                                   \
          "r"(_parity)                                                         \
          : "memory");                                                         \
    }                                                                          \
  } while (0)

#define MBARRIER_WAIT_PARITY_RELAXED(mbar_smem_addr, phase_parity)             \
  do {                                                                         \
    uint32_t _mbar = (uint32_t)(mbar_smem_addr);                               \
    uint32_t _parity = (uint32_t)(phase_parity);                               \
    uint32_t _done;                                                            \
    asm volatile(                                                              \
        "{\n\t.reg .pred p;\n\t"                                               \
        "mbarrier.try_wait.parity.relaxed.cta.shared::cta.b64 p, [%1], %2;\n\t" \
        "selp.b32 %0, 1, 0, p;\n\t}"                                           \
        : "=r"(_done)                                                          \
        : "r"(_mbar), "r"(_parity)                                             \
        : "memory");                                                           \
    if (!_done) {                                                              \
      asm volatile(                                                            \
          "{\n\t.reg .pred P1;\n\t"                                            \
          "WAIT_LOOP_%=:\n\t"                                                  \
          "mbarrier.try_wait.parity.relaxed.cta.shared::cta.b64 P1, [%0], %1, 0x989680;\n\t" \
          "@P1 bra.uni WAIT_DONE_%=;\n\t"                                      \
          "bra.uni WAIT_LOOP_%=;\n\t"                                          \
          "WAIT_DONE_%=:\n\t}" ::"r"(_mbar),                                   \
          "r"(_parity)                                                         \
          : "memory");                                                         \
    }                                                                          \
  } while (0)

#define LDSM_X4(r0, r1, r2, r3, addr)                                 \
  asm volatile(                                                       \
      "ldmatrix.sync.aligned.m8n8.x4.shared.b16 {%0,%1,%2,%3}, [%4];" \
      : "=r"(r0), "=r"(r1), "=r"(r2), "=r"(r3)                        \
      : "r"(addr))

#define MMA16816(c0, c1, c2, c3, a0, a1, a2, a3, b0, b1)              \
  asm volatile(                                                       \
      "mma.sync.aligned.m16n8k16.row.col.f32.f16.f16.f32 "            \
      "{%0,%1,%2,%3}, {%4,%5,%6,%7}, {%8,%9}, {%0,%1,%2,%3};"         \
      : "+f"(c0), "+f"(c1), "+f"(c2), "+f"(c3)                        \
      : "r"(a0), "r"(a1), "r"(a2), "r"(a3), "r"(b0), "r"(b1))

// ---------------------------- fused pre-kernel ------------------------------

static constexpr int DQ_BLOCKS = (N_TOTAL * K_TOTAL / 8) / 256;  // 8192
static constexpr int CV_BLOCKS = (M_TOTAL * K_TOTAL / 8) / 256;  // 16384

__global__ void k_prep(const int4* __restrict__ codes,
                       const float* __restrict__ scale,
                       const float4* __restrict__ x4) {
  if (blockIdx.x < DQ_BLOCKS) {
    __shared__ float cb[16];
    if (threadIdx.x < 16) cb[threadIdx.x] = c_nf4[threadIdx.x];
    __syncthreads();
    int t = blockIdx.x * 256 + threadIdx.x;
    int4 e = codes[t];
    float s = scale[t >> 9];
    uint4 o;
    __half2 h;
    h = __floats2half2_rn(cb[e.x & 15] * s, cb[(e.x >> 4) & 15] * s);
    o.x = reinterpret_cast<uint32_t&>(h);
    h = __floats2half2_rn(cb[e.y & 15] * s, cb[(e.y >> 4) & 15] * s);
    o.y = reinterpret_cast<uint32_t&>(h);
    h = __floats2half2_rn(cb[e.z & 15] * s, cb[(e.z >> 4) & 15] * s);
    o.z = reinterpret_cast<uint32_t&>(h);
    h = __floats2half2_rn(cb[e.w & 15] * s, cb[(e.w >> 4) & 15] * s);
    o.w = reinterpret_cast<uint32_t&>(h);
    reinterpret_cast<uint4*>(g_Wh)[t] = o;
  } else {
    int t = (blockIdx.x - DQ_BLOCKS) * 256 + threadIdx.x;
    float4 v0 = x4[2 * t];
    float4 v1 = x4[2 * t + 1];
    uint4 u;
    __half2 h;
    h = __floats2half2_rn(v0.x, v0.y);
    u.x = reinterpret_cast<uint32_t&>(h);
    h = __floats2half2_rn(v0.z, v0.w);
    u.y = reinterpret_cast<uint32_t&>(h);
    h = __floats2half2_rn(v1.x, v1.y);
    u.z = reinterpret_cast<uint32_t&>(h);
    h = __floats2half2_rn(v1.z, v1.w);
    u.w = reinterpret_cast<uint32_t&>(h);
    reinterpret_cast<uint4*>(g_Xh)[t] = u;
  }
}

// ------------------------------- GEMM kernel -------------------------------
// 160 threads: warps 0-3 = consumers (2x2 grid of 64x64 warp tiles),
// warp 4 = producer (all cp.async fills). 3-stage ring, 2 CTAs/SM.
// full[s]: count 32 (producer cp.async arrive.noinc)
// empty[s]: count 128 (consumer release arrives)

__global__ __launch_bounds__(160, 2) void k_gemm(const float* __restrict__ bias,
                                                 float* __restrict__ out) {
  extern __shared__ char smem[];
  const uint32_t sb = smem_u32(smem);
  const int tid = threadIdx.x;
  const int wid = tid >> 5;
  const int lid = tid & 31;
  const int n0 = blockIdx.x * BN;
  const int m0 = blockIdx.y * BM;

  if (tid == 0) {
#pragma unroll
    for (int s = 0; s < STAGES; ++s) {
      MBARRIER_INIT(sb + 8 * s, 32);        // full[s]: producer warp
      MBARRIER_INIT(sb + 24 + 8 * s, 128);  // empty[s]: consumer threads
    }
  }
  __syncthreads();

  if (wid == 4) {
    // ============================ PRODUCER ================================
    const int pl = lid;          // 0..31
    const int u = pl & 7;        // 16B column
    const int r0 = pl >> 3;      // base row 0..3
    const __half* aS = g_Xh + ((size_t)(m0 + r0) * K_TOTAL + u * 8);
    const __half* bS = g_Wh + ((size_t)(n0 + r0) * K_TOTAL + u * 8);
    const uint32_t swb = (uint32_t)(r0 * 128 + u * 16);

    int sp = 0, pp = 1;  // fresh-barrier parity: first STAGES waits pass
    for (int kt = 0; kt < KITERS; ++kt) {
      MBARRIER_WAIT_PARITY_RELAXED(sb + 24 + 8 * sp, pp);
      const uint32_t stage = sb + SM_STAGE0 + sp * STAGE_BYTES;
      const size_t kOff = (size_t)kt * BK;
#pragma unroll
      for (int i = 0; i < 32; ++i) {  // A: 128 rows, 4-row stride per lane
        CP_ASYNC16(stage + SWZ128(swb + (uint32_t)(i * 4 * 128)),
                   (const void*)(aS + kOff + (size_t)4 * i * K_TOTAL));
      }
#pragma unroll
      for (int i = 0; i < 32; ++i) {  // B: 128 rows
        CP_ASYNC16(stage + A_BYTES + SWZ128(swb + (uint32_t)(i * 4 * 128)),
                   (const void*)(bS + kOff + (size_t)4 * i * K_TOTAL));
      }
      CP_ASYNC_MBAR_ARRIVE(sb + 8 * sp);
      sp = (sp == 2) ? 0 : sp + 1;
      if (sp == 0) pp ^= 1;
    }
    return;
  }

  // ============================== CONSUMERS ================================
  const int wm = wid & 1;   // 0..1 -> 64-row slice
  const int wn = wid >> 1;  // 0..1 -> 64-col slice

  float c[4][8][4];
#pragma unroll
  for (int i = 0; i < 4; ++i)
#pragma unroll
    for (int j = 0; j < 8; ++j)
#pragma unroll
      for (int v = 0; v < 4; ++v) c[i][j][v] = 0.f;

  const int a_row = wm * 64 + (lid & 15);
  const int a_kb = (lid >> 4) * 16;
  const int b_row = wn * 64 + ((lid >> 4) * 8) + (lid & 7);
  const int b_kb = ((lid >> 3) & 1) * 16;

  int sc = 0, cpar = 0;

  for (int kt = 0; kt < KITERS; ++kt) {
    MBARRIER_WAIT_PARITY(sb + 8 * sc, cpar);
    const uint32_t aBase = sb + SM_STAGE0 + sc * STAGE_BYTES;
    const uint32_t bBase = aBase + A_BYTES;

    // ---- ks = 0..2: split-wave consume ----
#pragma unroll
    for (int ks = 0; ks < 3; ++ks) {
      uint32_t a[4][4], b[4][4];
#pragma unroll
      for (int mt = 0; mt < 2; ++mt) {
        uint32_t off = (uint32_t)((a_row + mt * 16) * 128 + ks * 32 + a_kb);
        LDSM_X4(a[mt][0], a[mt][1], a[mt][2], a[mt][3], aBase + SWZ128(off));
      }
#pragma unroll
      for (int p = 0; p < 2; ++p) {
        uint32_t off = (uint32_t)((b_row + p * 16) * 128 + ks * 32 + b_kb);
        LDSM_X4(b[p][0], b[p][1], b[p][2], b[p][3], bBase + SWZ128(off));
      }
#pragma unroll
      for (int mt = 0; mt < 2; ++mt)
#pragma unroll
        for (int nt = 0; nt < 4; ++nt)
          MMA16816(c[mt][nt][0], c[mt][nt][1], c[mt][nt][2], c[mt][nt][3],
                   a[mt][0], a[mt][1], a[mt][2], a[mt][3],
                   b[nt >> 1][(nt & 1) * 2], b[nt >> 1][(nt & 1) * 2 + 1]);
#pragma unroll
      for (int mt = 2; mt < 4; ++mt) {
        uint32_t off = (uint32_t)((a_row + mt * 16) * 128 + ks * 32 + a_kb);
        LDSM_X4(a[mt][0], a[mt][1], a[mt][2], a[mt][3], aBase + SWZ128(off));
      }
#pragma unroll
      for (int p = 2; p < 4; ++p) {
        uint32_t off = (uint32_t)((b_row + p * 16) * 128 + ks * 32 + b_kb);
        LDSM_X4(b[p][0], b[p][1], b[p][2], b[p][3], bBase + SWZ128(off));
      }
#pragma unroll
      for (int mt = 0; mt < 2; ++mt)
#pragma unroll
        for (int nt = 4; nt < 8; ++nt)
          MMA16816(c[mt][nt][0], c[mt][nt][1], c[mt][nt][2], c[mt][nt][3],
                   a[mt][0], a[mt][1], a[mt][2], a[mt][3],
                   b[nt >> 1][(nt & 1) * 2], b[nt >> 1][(nt & 1) * 2 + 1]);
#pragma unroll
      for (int mt = 2; mt < 4; ++mt)
#pragma unroll
        for (int nt = 0; nt < 8; ++nt)
          MMA16816(c[mt][nt][0], c[mt][nt][1], c[mt][nt][2], c[mt][nt][3],
                   a[mt][0], a[mt][1], a[mt][2], a[mt][3],
                   b[nt >> 1][(nt & 1) * 2], b[nt >> 1][(nt & 1) * 2 + 1]);
    }

    // ---- ks = 3: all LDSM -> early release -> MMAs ----
    {
      const int ks = 3;
      uint32_t a[4][4], b[4][4];
#pragma unroll
      for (int mt = 0; mt < 4; ++mt) {
        uint32_t off = (uint32_t)((a_row + mt * 16) * 128 + ks * 32 + a_kb);
        LDSM_X4(a[mt][0], a[mt][1], a[mt][2], a[mt][3], aBase + SWZ128(off));
      }
#pragma unroll
      for (int p = 0; p < 4; ++p) {
        uint32_t off = (uint32_t)((b_row + p * 16) * 128 + ks * 32 + b_kb);
        LDSM_X4(b[p][0], b[p][1], b[p][2], b[p][3], bBase + SWZ128(off));
      }
      MBARRIER_ARRIVE(sb + 24 + 8 * sc);  // release stage to producer
#pragma unroll
      for (int mt = 0; mt < 4; ++mt)
#pragma unroll
        for (int nt = 0; nt < 8; ++nt)
          MMA16816(c[mt][nt][0], c[mt][nt][1], c[mt][nt][2], c[mt][nt][3],
                   a[mt][0], a[mt][1], a[mt][2], a[mt][3],
                   b[nt >> 1][(nt & 1) * 2], b[nt >> 1][(nt & 1) * 2 + 1]);
    }

    sc = (sc == 2) ? 0 : sc + 1;
    if (sc == 0) cpar ^= 1;
  }

  // ------------------------------ epilogue ---------------------------------
  const int mrow = m0 + wm * 64 + (lid >> 2);
  const int ncol = n0 + wn * 64 + (lid & 3) * 2;
#pragma unroll
  for (int mt = 0; mt < 4; ++mt) {
#pragma unroll
    for (int nt = 0; nt < 8; ++nt) {
      const float2 b2 = *reinterpret_cast<const float2*>(bias + ncol + nt * 8);
      float* p0 = out + (size_t)(mrow + mt * 16) * N_TOTAL + ncol + nt * 8;
      float* p1 = p0 + 8 * N_TOTAL;
      float2 v0 = {c[mt][nt][0] + b2.x, c[mt][nt][1] + b2.y};
      float2 v1 = {c[mt][nt][2] + b2.x, c[mt][nt][3] + b2.y};
      *reinterpret_cast<float2*>(p0) = v0;
      *reinterpret_cast<float2*>(p1) = v1;
    }
  }
}

// ------------------------------- launcher ----------------------------------

extern "C" void kernel_launch(void* const* d_in, const int* in_sizes, int n_in,
                              void* d_out, int out_size) {
  const float* x = (const float*)d_in[0];
  const int* codes = (const int*)d_in[1];
  const float* scale = (const float*)d_in[2];
  const float* bias = (const float*)d_in[3];
  float* out = (float*)d_out;

  k_prep<<<DQ_BLOCKS + CV_BLOCKS, 256>>>((const int4*)codes, scale,
                                         (const float4*)x);

  cudaFuncSetAttribute(k_gemm, cudaFuncAttributeMaxDynamicSharedMemorySize,
                       SMEM_BYTES);
  dim3 grid(N_TOTAL / BN, M_TOTAL / BM);  // (32, 64)
  k_gemm<<<grid, 160, SMEM_BYTES>>>(bias, out);
}

// round 12
// speedup vs baseline: 1.2350x; 1.2350x over previous
#include <cuda_runtime.h>
#include <cuda_fp16.h>
#include <cstdint>

// ---------------------------------------------------------------------------
// out[b,s,o] = sum_i x[b,s,i] * (nf4[codes][o,i] * scale[o]) + bias[o]
// M = 8192, N = 4096, K = 4096, fp32 in/out.
// Plain sm_103 target (no tcgen05) -> legacy HMMA m16n8k16 pipe.
// R12: R9 base + ks-level fragment double buffering (regs available: 256/thr
// at 2 CTAs/SM). LDSM for ks+1 issues before ks's MMAs; stage release and
// producer seal move one ks earlier (ks2).
// ---------------------------------------------------------------------------

static constexpr int M_TOTAL = 8192;
static constexpr int N_TOTAL = 4096;
static constexpr int K_TOTAL = 4096;

static constexpr int BM = 128;
static constexpr int BN = 128;
static constexpr int BK = 64;            // 64 halfs = 128 B/row (SW128)
static constexpr int STAGES = 3;
static constexpr int KITERS = K_TOTAL / BK;  // 64

static constexpr int A_BYTES = BM * 128;                 // 16 KB
static constexpr int B_BYTES = BN * 128;                 // 16 KB
static constexpr int STAGE_BYTES = A_BYTES + B_BYTES;    // 32 KB
static constexpr int SM_STAGE0 = 1024;
static constexpr int SMEM_BYTES = SM_STAGE0 + STAGES * STAGE_BYTES;  // 99328

__device__ __align__(1024) __half g_Wh[(size_t)N_TOTAL * K_TOTAL];  // 32 MB
__device__ __align__(1024) __half g_Xh[(size_t)M_TOTAL * K_TOTAL];  // 64 MB

__constant__ float c_nf4[16] = {
    -1.0f, -0.6961928f, -0.52507305f, -0.3949175f, -0.28444138f, -0.18477343f,
    -0.09105004f, 0.0f, 0.0795803f, 0.1609302f, 0.2461123f, 0.33791524f,
    0.44070983f, 0.562617f, 0.72295684f, 1.0f};

// ------------------------------- helpers -----------------------------------

__device__ __forceinline__ uint32_t smem_u32(const void* p) {
  uint32_t a;
  asm("{ .reg .u64 t; cvta.to.shared.u64 t, %1; cvt.u32.u64 %0, t; }"
      : "=r"(a) : "l"(p));
  return a;
}

#define SWZ128(b) ((b) ^ (((b) >> 3) & 0x70))

#define CP_ASYNC16(dst, gsrc)                                          \
  asm volatile("cp.async.cg.shared.global [%0], [%1], 16;" ::"r"(dst), \
               "l"(gsrc)                                               \
               : "memory")

#define CP_ASYNC_MBAR_ARRIVE(mbar)                                           \
  asm volatile("cp.async.mbarrier.arrive.noinc.shared::cta.b64 [%0];" ::"r"( \
                   (uint32_t)(mbar))                                         \
               : "memory")

#define MBARRIER_INIT(addr, cnt)                                             \
  asm volatile("mbarrier.init.shared.b64 [%0], %1;" ::"r"((uint32_t)(addr)), \
               "r"((uint32_t)(cnt))                                          \
               : "memory")

#define MBARRIER_ARRIVE(addr)                               \
  asm volatile("mbarrier.arrive.shared.b64 _, [%0];" ::"r"( \
                   (uint32_t)(addr))                        \
               : "memory")

#define MBARRIER_PROBE(res, mbar_smem_addr, phase_parity)                      \
  asm volatile(                                                                \
      "{\n\t.reg .pred p;\n\t"                                                 \
      "mbarrier.test_wait.parity.acquire.cta.shared::cta.b64 p, [%1], %2;\n\t" \
      "selp.b32 %0, 1, 0, p;\n\t}"                                             \
      : "=r"(res)                                                              \
      : "r"((uint32_t)(mbar_smem_addr)), "r"((uint32_t)(phase_parity))         \
      : "memory")

#define MBARRIER_WAIT_PARITY(mbar_smem_addr, phase_parity)                     \
  do {                                                                         \
    uint32_t _mbar = (uint32_t)(mbar_smem_addr);                               \
    uint32_t _parity = (uint32_t)(phase_parity);                               \
    uint32_t _done;                                                            \
    asm volatile(                                                              \
        "{\n\t.reg .pred p;\n\t"                                               \
        "mbarrier.try_wait.parity.acquire.cta.shared::cta.b64 p, [%1], %2;\n\t" \
        "selp.b32 %0, 1, 0, p;\n\t}"                                           \
        : "=r"(_done)                                                          \
        : "r"(_mbar), "r"(_parity)                                             \
        : "memory");                                                           \
    if (!_done) {                                                              \
      asm volatile(                                                            \
          "{\n\t.reg .pred P1;\n\t"                                            \
          "WAIT_LOOP_%=:\n\t"                                                  \
          "mbarrier.try_wait.parity.acquire.cta.shared::cta.b64 P1, [%0], %1, 0x989680;\n\t" \
          "@P1 bra.uni WAIT_DONE_%=;\n\t"                                      \
          "bra.uni WAIT_LOOP_%=;\n\t"                                          \
          "WAIT_DONE_%=:\n\t}" ::"r"(_mbar),                                   \
          "r"(_parity)                                                         \
          : "memory");                                                         \
    }                                                                          \
  } while (0)

#define MBARRIER_WAIT_PARITY_RELAXED(mbar_smem_addr, phase_parity)             \
  do {                                                                         \
    uint32_t _mbar = (uint32_t)(mbar_smem_addr);                               \
    uint32_t _parity = (uint32_t)(phase_parity);                               \
    uint32_t _done;                                                            \
    asm volatile(                                                              \
        "{\n\t.reg .pred p;\n\t"                                               \
        "mbarrier.try_wait.parity.relaxed.cta.shared::cta.b64 p, [%1], %2;\n\t" \
        "selp.b32 %0, 1, 0, p;\n\t}"                                           \
        : "=r"(_done)                                                          \
        : "r"(_mbar), "r"(_parity)                                             \
        : "memory");                                                           \
    if (!_done) {                                                              \
      asm volatile(                                                            \
          "{\n\t.reg .pred P1;\n\t"                                            \
          "WAIT_LOOP_%=:\n\t"                                                  \
          "mbarrier.try_wait.parity.relaxed.cta.shared::cta.b64 P1, [%0], %1, 0x989680;\n\t" \
          "@P1 bra.uni WAIT_DONE_%=;\n\t"                                      \
          "bra.uni WAIT_LOOP_%=;\n\t"                                          \
          "WAIT_DONE_%=:\n\t}" ::"r"(_mbar),                                   \
          "r"(_parity)                                                         \
          : "memory");                                                         \
    }                                                                          \
  } while (0)

#define LDSM_X4(r0, r1, r2, r3, addr)                                 \
  asm volatile(                                                       \
      "ldmatrix.sync.aligned.m8n8.x4.shared.b16 {%0,%1,%2,%3}, [%4];" \
      : "=r"(r0), "=r"(r1), "=r"(r2), "=r"(r3)                        \
      : "r"(addr))

#define MMA16816(c0, c1, c2, c3, a0, a1, a2, a3, b0, b1)              \
  asm volatile(                                                       \
      "mma.sync.aligned.m16n8k16.row.col.f32.f16.f16.f32 "            \
      "{%0,%1,%2,%3}, {%4,%5,%6,%7}, {%8,%9}, {%0,%1,%2,%3};"         \
      : "+f"(c0), "+f"(c1), "+f"(c2), "+f"(c3)                        \
      : "r"(a0), "r"(a1), "r"(a2), "r"(a3), "r"(b0), "r"(b1))

// ---------------------------- fused pre-kernel ------------------------------

static constexpr int DQ_BLOCKS = (N_TOTAL * K_TOTAL / 8) / 256;  // 8192
static constexpr int CV_BLOCKS = (M_TOTAL * K_TOTAL / 8) / 256;  // 16384

__global__ void k_prep(const int4* __restrict__ codes,
                       const float* __restrict__ scale,
                       const float4* __restrict__ x4) {
  if (blockIdx.x < DQ_BLOCKS) {
    __shared__ float cb[16];
    if (threadIdx.x < 16) cb[threadIdx.x] = c_nf4[threadIdx.x];
    __syncthreads();
    int t = blockIdx.x * 256 + threadIdx.x;
    int4 e = codes[t];
    float s = scale[t >> 9];
    uint4 o;
    __half2 h;
    h = __floats2half2_rn(cb[e.x & 15] * s, cb[(e.x >> 4) & 15] * s);
    o.x = reinterpret_cast<uint32_t&>(h);
    h = __floats2half2_rn(cb[e.y & 15] * s, cb[(e.y >> 4) & 15] * s);
    o.y = reinterpret_cast<uint32_t&>(h);
    h = __floats2half2_rn(cb[e.z & 15] * s, cb[(e.z >> 4) & 15] * s);
    o.z = reinterpret_cast<uint32_t&>(h);
    h = __floats2half2_rn(cb[e.w & 15] * s, cb[(e.w >> 4) & 15] * s);
    o.w = reinterpret_cast<uint32_t&>(h);
    reinterpret_cast<uint4*>(g_Wh)[t] = o;
  } else {
    int t = (blockIdx.x - DQ_BLOCKS) * 256 + threadIdx.x;
    float4 v0 = x4[2 * t];
    float4 v1 = x4[2 * t + 1];
    uint4 u;
    __half2 h;
    h = __floats2half2_rn(v0.x, v0.y);
    u.x = reinterpret_cast<uint32_t&>(h);
    h = __floats2half2_rn(v0.z, v0.w);
    u.y = reinterpret_cast<uint32_t&>(h);
    h = __floats2half2_rn(v1.x, v1.y);
    u.z = reinterpret_cast<uint32_t&>(h);
    h = __floats2half2_rn(v1.z, v1.w);
    u.w = reinterpret_cast<uint32_t&>(h);
    reinterpret_cast<uint4*>(g_Xh)[t] = u;
  }
}

// ------------------------------- GEMM kernel -------------------------------

__global__ __launch_bounds__(128, 2) void k_gemm(const float* __restrict__ bias,
                                                 float* __restrict__ out) {
  extern __shared__ char smem[];
  const uint32_t sb = smem_u32(smem);
  const int tid = threadIdx.x;
  const int wid = tid >> 5;
  const int lid = tid & 31;
  const int wm = wid & 1;
  const int wn = wid >> 1;
  const int n0 = blockIdx.x * BN;
  const int m0 = blockIdx.y * BM;

  if (tid == 0) {
#pragma unroll
    for (int s = 0; s < STAGES; ++s) {
      MBARRIER_INIT(sb + 8 * s, 128);       // full[s]
      MBARRIER_INIT(sb + 24 + 8 * s, 128);  // empty[s]
    }
  }
  __syncthreads();

  float c[4][8][4];
#pragma unroll
  for (int i = 0; i < 4; ++i)
#pragma unroll
    for (int j = 0; j < 8; ++j)
#pragma unroll
      for (int v = 0; v < 4; ++v) c[i][j][v] = 0.f;

  const int f_row = tid >> 3;  // 0..15
  const int f_u = tid & 7;
  const uint32_t f_sw_base = (uint32_t)(f_row * 128 + f_u * 16);
  const __half* aSrc0 = g_Xh + ((size_t)(m0 + f_row) * K_TOTAL + f_u * 8);
  const __half* bSrc0 = g_Wh + ((size_t)(n0 + f_row) * K_TOTAL + f_u * 8);

  auto fill_part = [&](int s, int ktp, int part) {
    const uint32_t stage = sb + SM_STAGE0 + s * STAGE_BYTES;
    const size_t kOff = (size_t)ktp * BK;
#pragma unroll
    for (int j = 0; j < 2; ++j) {
      const int i = part * 2 + j;  // 0..7
      CP_ASYNC16(stage + SWZ128(f_sw_base + (uint32_t)(i * 16 * 128)),
                 (const void*)(aSrc0 + kOff + (size_t)16 * i * K_TOTAL));
    }
#pragma unroll
    for (int j = 0; j < 2; ++j) {
      const int i = part * 2 + j;
      CP_ASYNC16(stage + A_BYTES +
                     SWZ128(f_sw_base + (uint32_t)(i * 16 * 128)),
                 (const void*)(bSrc0 + kOff + (size_t)16 * i * K_TOTAL));
    }
  };

  // prologue: fill stages 0,1
#pragma unroll
  for (int p = 0; p < 4; ++p) fill_part(0, 0, p);
  CP_ASYNC_MBAR_ARRIVE(sb + 8 * 0);
#pragma unroll
  for (int p = 0; p < 4; ++p) fill_part(1, 1, p);
  CP_ASYNC_MBAR_ARRIVE(sb + 8 * 1);

  const int a_row = wm * 64 + (lid & 15);
  const int a_kb = (lid >> 4) * 16;
  const int b_row = wn * 64 + ((lid >> 4) * 8) + (lid & 7);
  const int b_kb = ((lid >> 3) & 1) * 16;

  int sp = 2, pp = 1;    // produce stage/parity
  int sc = 0, cpar = 0;  // consume stage/parity
  uint32_t pF = 0;       // probe-ahead result

  for (int kt = 0; kt < KITERS; ++kt) {
    const bool produce = (kt + 2 < KITERS);
    const int nsc = (sc == 2) ? 0 : sc + 1;
    const int ncp = (nsc == 0) ? (cpar ^ 1) : cpar;

    if (!pF) MBARRIER_WAIT_PARITY(sb + 8 * sc, cpar);
    pF = 0;
    const uint32_t aBase = sb + SM_STAGE0 + sc * STAGE_BYTES;
    const uint32_t bBase = aBase + A_BYTES;

    uint32_t a[2][4][4], b[2][4][4];

    // preload ks=0 fragments into buffer 0
#pragma unroll
    for (int mt = 0; mt < 4; ++mt) {
      uint32_t off = (uint32_t)((a_row + mt * 16) * 128 + a_kb);
      LDSM_X4(a[0][mt][0], a[0][mt][1], a[0][mt][2], a[0][mt][3],
              aBase + SWZ128(off));
    }
#pragma unroll
    for (int p = 0; p < 4; ++p) {
      uint32_t off = (uint32_t)((b_row + p * 16) * 128 + b_kb);
      LDSM_X4(b[0][p][0], b[0][p][1], b[0][p][2], b[0][p][3],
              bBase + SWZ128(off));
    }

#pragma unroll
    for (int ks = 0; ks < 4; ++ks) {
      const int cb = ks & 1;
      const int nb = cb ^ 1;
      if (ks < 3) {  // prefetch ks+1 frags into the other buffer
#pragma unroll
        for (int mt = 0; mt < 4; ++mt) {
          uint32_t off =
              (uint32_t)((a_row + mt * 16) * 128 + (ks + 1) * 32 + a_kb);
          LDSM_X4(a[nb][mt][0], a[nb][mt][1], a[nb][mt][2], a[nb][mt][3],
                  aBase + SWZ128(off));
        }
#pragma unroll
        for (int p = 0; p < 4; ++p) {
          uint32_t off =
              (uint32_t)((b_row + p * 16) * 128 + (ks + 1) * 32 + b_kb);
          LDSM_X4(b[nb][p][0], b[nb][p][1], b[nb][p][2], b[nb][p][3],
                  bBase + SWZ128(off));
        }
      }
      if (ks == 1 && produce) {
        MBARRIER_WAIT_PARITY_RELAXED(sb + 24 + 8 * sp, pp);
        fill_part(sp, kt + 2, 0);
        fill_part(sp, kt + 2, 1);
      }
      if (ks == 2) {
        if (produce) {
          fill_part(sp, kt + 2, 2);
          fill_part(sp, kt + 2, 3);
          CP_ASYNC_MBAR_ARRIVE(sb + 8 * sp);  // seal produced stage
        }
        MBARRIER_ARRIVE(sb + 24 + 8 * sc);  // all LDSMs of stage issued
        MBARRIER_PROBE(pF, sb + 8 * nsc, ncp);
      }
#pragma unroll
      for (int mt = 0; mt < 4; ++mt)
#pragma unroll
        for (int nt = 0; nt < 8; ++nt)
          MMA16816(c[mt][nt][0], c[mt][nt][1], c[mt][nt][2], c[mt][nt][3],
                   a[cb][mt][0], a[cb][mt][1], a[cb][mt][2], a[cb][mt][3],
                   b[cb][nt >> 1][(nt & 1) * 2],
                   b[cb][nt >> 1][(nt & 1) * 2 + 1]);
    }

    sp = (sp == 2) ? 0 : sp + 1;
    if (sp == 0) pp ^= 1;
    sc = nsc;
    cpar = ncp;
  }

  // ------------------------------ epilogue ---------------------------------
  const int mrow = m0 + wm * 64 + (lid >> 2);
  const int ncol = n0 + wn * 64 + (lid & 3) * 2;
#pragma unroll
  for (int mt = 0; mt < 4; ++mt) {
#pragma unroll
    for (int nt = 0; nt < 8; ++nt) {
      const float2 b2 = *reinterpret_cast<const float2*>(bias + ncol + nt * 8);
      float* p0 = out + (size_t)(mrow + mt * 16) * N_TOTAL + ncol + nt * 8;
      float* p1 = p0 + 8 * N_TOTAL;
      float2 v0 = {c[mt][nt][0] + b2.x, c[mt][nt][1] + b2.y};
      float2 v1 = {c[mt][nt][2] + b2.x, c[mt][nt][3] + b2.y};
      *reinterpret_cast<float2*>(p0) = v0;
      *reinterpret_cast<float2*>(p1) = v1;
    }
  }
}

// ------------------------------- launcher ----------------------------------

extern "C" void kernel_launch(void* const* d_in, const int* in_sizes, int n_in,
                              void* d_out, int out_size) {
  const float* x = (const float*)d_in[0];
  const int* codes = (const int*)d_in[1];
  const float* scale = (const float*)d_in[2];
  const float* bias = (const float*)d_in[3];
  float* out = (float*)d_out;

  k_prep<<<DQ_BLOCKS + CV_BLOCKS, 256>>>((const int4*)codes, scale,
                                         (const float4*)x);

  cudaFuncSetAttribute(k_gemm, cudaFuncAttributeMaxDynamicSharedMemorySize,
                       SMEM_BYTES);
  dim3 grid(N_TOTAL / BN, M_TOTAL / BM);  // (32, 64)
  k_gemm<<<grid, 128, SMEM_BYTES>>>(bias, out);
}

// round 13
// speedup vs baseline: 1.2363x; 1.0011x over previous
#include <cuda_runtime.h>
#include <cuda_fp16.h>
#include <cstdint>

// ---------------------------------------------------------------------------
// out[b,s,o] = sum_i x[b,s,i] * (nf4[codes][o,i] * scale[o]) + bias[o]
// M = 8192, N = 4096, K = 4096, fp32 in/out.
// Plain sm_103 target (no tcgen05) -> legacy HMMA m16n8k16 pipe.
// R13: GEMM identical to R12 (best: 541.4us, tensor 83.9%). Prep reworked:
// interleaved dequant/convert block assignment (both DRAM streams active the
// whole time) + two independent load/store chains per thread (higher MLP).
// ---------------------------------------------------------------------------

static constexpr int M_TOTAL = 8192;
static constexpr int N_TOTAL = 4096;
static constexpr int K_TOTAL = 4096;

static constexpr int BM = 128;
static constexpr int BN = 128;
static constexpr int BK = 64;            // 64 halfs = 128 B/row (SW128)
static constexpr int STAGES = 3;
static constexpr int KITERS = K_TOTAL / BK;  // 64

static constexpr int A_BYTES = BM * 128;                 // 16 KB
static constexpr int B_BYTES = BN * 128;                 // 16 KB
static constexpr int STAGE_BYTES = A_BYTES + B_BYTES;    // 32 KB
static constexpr int SM_STAGE0 = 1024;
static constexpr int SMEM_BYTES = SM_STAGE0 + STAGES * STAGE_BYTES;  // 99328

__device__ __align__(1024) __half g_Wh[(size_t)N_TOTAL * K_TOTAL];  // 32 MB
__device__ __align__(1024) __half g_Xh[(size_t)M_TOTAL * K_TOTAL];  // 64 MB

__constant__ float c_nf4[16] = {
    -1.0f, -0.6961928f, -0.52507305f, -0.3949175f, -0.28444138f, -0.18477343f,
    -0.09105004f, 0.0f, 0.0795803f, 0.1609302f, 0.2461123f, 0.33791524f,
    0.44070983f, 0.562617f, 0.72295684f, 1.0f};

// ------------------------------- helpers -----------------------------------

__device__ __forceinline__ uint32_t smem_u32(const void* p) {
  uint32_t a;
  asm("{ .reg .u64 t; cvta.to.shared.u64 t, %1; cvt.u32.u64 %0, t; }"
      : "=r"(a) : "l"(p));
  return a;
}

#define SWZ128(b) ((b) ^ (((b) >> 3) & 0x70))

#define CP_ASYNC16(dst, gsrc)                                          \
  asm volatile("cp.async.cg.shared.global [%0], [%1], 16;" ::"r"(dst), \
               "l"(gsrc)                                               \
               : "memory")

#define CP_ASYNC_MBAR_ARRIVE(mbar)                                           \
  asm volatile("cp.async.mbarrier.arrive.noinc.shared::cta.b64 [%0];" ::"r"( \
                   (uint32_t)(mbar))                                         \
               : "memory")

#define MBARRIER_INIT(addr, cnt)                                             \
  asm volatile("mbarrier.init.shared.b64 [%0], %1;" ::"r"((uint32_t)(addr)), \
               "r"((uint32_t)(cnt))                                          \
               : "memory")

#define MBARRIER_ARRIVE(addr)                               \
  asm volatile("mbarrier.arrive.shared.b64 _, [%0];" ::"r"( \
                   (uint32_t)(addr))                        \
               : "memory")

#define MBARRIER_PROBE(res, mbar_smem_addr, phase_parity)                      \
  asm volatile(                                                                \
      "{\n\t.reg .pred p;\n\t"                                                 \
      "mbarrier.test_wait.parity.acquire.cta.shared::cta.b64 p, [%1], %2;\n\t" \
      "selp.b32 %0, 1, 0, p;\n\t}"                                             \
      : "=r"(res)                                                              \
      : "r"((uint32_t)(mbar_smem_addr)), "r"((uint32_t)(phase_parity))         \
      : "memory")

#define MBARRIER_WAIT_PARITY(mbar_smem_addr, phase_parity)                     \
  do {                                                                         \
    uint32_t _mbar = (uint32_t)(mbar_smem_addr);                               \
    uint32_t _parity = (uint32_t)(phase_parity);                               \
    uint32_t _done;                                                            \
    asm volatile(                                                              \
        "{\n\t.reg .pred p;\n\t"                                               \
        "mbarrier.try_wait.parity.acquire.cta.shared::cta.b64 p, [%1], %2;\n\t" \
        "selp.b32 %0, 1, 0, p;\n\t}"                                           \
        : "=r"(_done)                                                          \
        : "r"(_mbar), "r"(_parity)                                             \
        : "memory");                                                           \
    if (!_done) {                                                              \
      asm volatile(                                                            \
          "{\n\t.reg .pred P1;\n\t"                                            \
          "WAIT_LOOP_%=:\n\t"                                                  \
          "mbarrier.try_wait.parity.acquire.cta.shared::cta.b64 P1, [%0], %1, 0x989680;\n\t" \
          "@P1 bra.uni WAIT_DONE_%=;\n\t"                                      \
          "bra.uni WAIT_LOOP_%=;\n\t"                                          \
          "WAIT_DONE_%=:\n\t}" ::"r"(_mbar),                                   \
          "r"(_parity)                                                         \
          : "memory");                                                         \
    }                                                                          \
  } while (0)

#define MBARRIER_WAIT_PARITY_RELAXED(mbar_smem_addr, phase_parity)             \
  do {                                                                         \
    uint32_t _mbar = (uint32_t)(mbar_smem_addr);                               \
    uint32_t _parity = (uint32_t)(phase_parity);                               \
    uint32_t _done;                                                            \
    asm volatile(                                                              \
        "{\n\t.reg .pred p;\n\t"                                               \
        "mbarrier.try_wait.parity.relaxed.cta.shared::cta.b64 p, [%1], %2;\n\t" \
        "selp.b32 %0, 1, 0, p;\n\t}"                                           \
        : "=r"(_done)                                                          \
        : "r"(_mbar), "r"(_parity)                                             \
        : "memory");                                                           \
    if (!_done) {                                                              \
      asm volatile(                                                            \
          "{\n\t.reg .pred P1;\n\t"                                            \
          "WAIT_LOOP_%=:\n\t"                                                  \
          "mbarrier.try_wait.parity.relaxed.cta.shared::cta.b64 P1, [%0], %1, 0x989680;\n\t" \
          "@P1 bra.uni WAIT_DONE_%=;\n\t"                                      \
          "bra.uni WAIT_LOOP_%=;\n\t"                                          \
          "WAIT_DONE_%=:\n\t}" ::"r"(_mbar),                                   \
          "r"(_parity)                                                         \
          : "memory");                                                         \
    }                                                                          \
  } while (0)

#define LDSM_X4(r0, r1, r2, r3, addr)                                 \
  asm volatile(                                                       \
      "ldmatrix.sync.aligned.m8n8.x4.shared.b16 {%0,%1,%2,%3}, [%4];" \
      : "=r"(r0), "=r"(r1), "=r"(r2), "=r"(r3)                        \
      : "r"(addr))

#define MMA16816(c0, c1, c2, c3, a0, a1, a2, a3, b0, b1)              \
  asm volatile(                                                       \
      "mma.sync.aligned.m16n8k16.row.col.f32.f16.f16.f32 "            \
      "{%0,%1,%2,%3}, {%4,%5,%6,%7}, {%8,%9}, {%0,%1,%2,%3};"         \
      : "+f"(c0), "+f"(c1), "+f"(c2), "+f"(c3)                        \
      : "r"(a0), "r"(a1), "r"(a2), "r"(a3), "r"(b0), "r"(b1))

// ---------------------------- fused pre-kernel ------------------------------
// Interleaved block assignment: bid%3==0 -> dequant (1/3 of 12288 blocks),
// else convert (2/3). Each thread: 32B output via two independent chains.

static constexpr int DQ_BLOCKS = (N_TOTAL * K_TOTAL / 16) / 256;  // 4096
static constexpr int CV_BLOCKS = (M_TOTAL * K_TOTAL / 16) / 256;  // 8192
static constexpr int PREP_BLOCKS = DQ_BLOCKS + CV_BLOCKS;         // 12288

__global__ void k_prep(const int4* __restrict__ codes,
                       const float* __restrict__ scale,
                       const float4* __restrict__ x4) {
  const int bid = blockIdx.x;
  if (bid % 3 == 0) {
    // ------------------------- dequant -------------------------
    __shared__ float cb[16];
    if (threadIdx.x < 16) cb[threadIdx.x] = c_nf4[threadIdx.x];
    __syncthreads();
    const int t = (bid / 3) * 256 + threadIdx.x;  // 0 .. 1048575
    // 8 ints = 16 weights; 2048 ints per out-row; 256 | 2048 -> no straddle
    const float s = scale[t >> 8];
    int4 e0 = codes[2 * t];
    int4 e1 = codes[2 * t + 1];
    uint4 o0, o1;
    __half2 h;
    h = __floats2half2_rn(cb[e0.x & 15] * s, cb[(e0.x >> 4) & 15] * s);
    o0.x = reinterpret_cast<uint32_t&>(h);
    h = __floats2half2_rn(cb[e0.y & 15] * s, cb[(e0.y >> 4) & 15] * s);
    o0.y = reinterpret_cast<uint32_t&>(h);
    h = __floats2half2_rn(cb[e0.z & 15] * s, cb[(e0.z >> 4) & 15] * s);
    o0.z = reinterpret_cast<uint32_t&>(h);
    h = __floats2half2_rn(cb[e0.w & 15] * s, cb[(e0.w >> 4) & 15] * s);
    o0.w = reinterpret_cast<uint32_t&>(h);
    h = __floats2half2_rn(cb[e1.x & 15] * s, cb[(e1.x >> 4) & 15] * s);
    o1.x = reinterpret_cast<uint32_t&>(h);
    h = __floats2half2_rn(cb[e1.y & 15] * s, cb[(e1.y >> 4) & 15] * s);
    o1.y = reinterpret_cast<uint32_t&>(h);
    h = __floats2half2_rn(cb[e1.z & 15] * s, cb[(e1.z >> 4) & 15] * s);
    o1.z = reinterpret_cast<uint32_t&>(h);
    h = __floats2half2_rn(cb[e1.w & 15] * s, cb[(e1.w >> 4) & 15] * s);
    o1.w = reinterpret_cast<uint32_t&>(h);
    reinterpret_cast<uint4*>(g_Wh)[2 * t] = o0;
    reinterpret_cast<uint4*>(g_Wh)[2 * t + 1] = o1;
  } else {
    // ------------------------- convert -------------------------
    const int cvb = 2 * (bid / 3) + (bid % 3) - 1;  // 0 .. CV_BLOCKS-1
    const int t = cvb * 256 + threadIdx.x;          // 0 .. 2097151
    // 16 floats in (4x float4), 16 halfs out (2x uint4)
    float4 v0 = x4[4 * t];
    float4 v1 = x4[4 * t + 1];
    float4 v2 = x4[4 * t + 2];
    float4 v3 = x4[4 * t + 3];
    uint4 u0, u1;
    __half2 h;
    h = __floats2half2_rn(v0.x, v0.y);
    u0.x = reinterpret_cast<uint32_t&>(h);
    h = __floats2half2_rn(v0.z, v0.w);
    u0.y = reinterpret_cast<uint32_t&>(h);
    h = __floats2half2_rn(v1.x, v1.y);
    u0.z = reinterpret_cast<uint32_t&>(h);
    h = __floats2half2_rn(v1.z, v1.w);
    u0.w = reinterpret_cast<uint32_t&>(h);
    h = __floats2half2_rn(v2.x, v2.y);
    u1.x = reinterpret_cast<uint32_t&>(h);
    h = __floats2half2_rn(v2.z, v2.w);
    u1.y = reinterpret_cast<uint32_t&>(h);
    h = __floats2half2_rn(v3.x, v3.y);
    u1.z = reinterpret_cast<uint32_t&>(h);
    h = __floats2half2_rn(v3.z, v3.w);
    u1.w = reinterpret_cast<uint32_t&>(h);
    reinterpret_cast<uint4*>(g_Xh)[2 * t] = u0;
    reinterpret_cast<uint4*>(g_Xh)[2 * t + 1] = u1;
  }
}

// ------------------------------- GEMM kernel -------------------------------
// Identical to R12 (best GEMM: 541.4us, tensor 83.9%).

__global__ __launch_bounds__(128, 2) void k_gemm(const float* __restrict__ bias,
                                                 float* __restrict__ out) {
  extern __shared__ char smem[];
  const uint32_t sb = smem_u32(smem);
  const int tid = threadIdx.x;
  const int wid = tid >> 5;
  const int lid = tid & 31;
  const int wm = wid & 1;
  const int wn = wid >> 1;
  const int n0 = blockIdx.x * BN;
  const int m0 = blockIdx.y * BM;

  if (tid == 0) {
#pragma unroll
    for (int s = 0; s < STAGES; ++s) {
      MBARRIER_INIT(sb + 8 * s, 128);       // full[s]
      MBARRIER_INIT(sb + 24 + 8 * s, 128);  // empty[s]
    }
  }
  __syncthreads();

  float c[4][8][4];
#pragma unroll
  for (int i = 0; i < 4; ++i)
#pragma unroll
    for (int j = 0; j < 8; ++j)
#pragma unroll
      for (int v = 0; v < 4; ++v) c[i][j][v] = 0.f;

  const int f_row = tid >> 3;  // 0..15
  const int f_u = tid & 7;
  const uint32_t f_sw_base = (uint32_t)(f_row * 128 + f_u * 16);
  const __half* aSrc0 = g_Xh + ((size_t)(m0 + f_row) * K_TOTAL + f_u * 8);
  const __half* bSrc0 = g_Wh + ((size_t)(n0 + f_row) * K_TOTAL + f_u * 8);

  auto fill_part = [&](int s, int ktp, int part) {
    const uint32_t stage = sb + SM_STAGE0 + s * STAGE_BYTES;
    const size_t kOff = (size_t)ktp * BK;
#pragma unroll
    for (int j = 0; j < 2; ++j) {
      const int i = part * 2 + j;  // 0..7
      CP_ASYNC16(stage + SWZ128(f_sw_base + (uint32_t)(i * 16 * 128)),
                 (const void*)(aSrc0 + kOff + (size_t)16 * i * K_TOTAL));
    }
#pragma unroll
    for (int j = 0; j < 2; ++j) {
      const int i = part * 2 + j;
      CP_ASYNC16(stage + A_BYTES +
                     SWZ128(f_sw_base + (uint32_t)(i * 16 * 128)),
                 (const void*)(bSrc0 + kOff + (size_t)16 * i * K_TOTAL));
    }
  };

  // prologue: fill stages 0,1
#pragma unroll
  for (int p = 0; p < 4; ++p) fill_part(0, 0, p);
  CP_ASYNC_MBAR_ARRIVE(sb + 8 * 0);
#pragma unroll
  for (int p = 0; p < 4; ++p) fill_part(1, 1, p);
  CP_ASYNC_MBAR_ARRIVE(sb + 8 * 1);

  const int a_row = wm * 64 + (lid & 15);
  const int a_kb = (lid >> 4) * 16;
  const int b_row = wn * 64 + ((lid >> 4) * 8) + (lid & 7);
  const int b_kb = ((lid >> 3) & 1) * 16;

  int sp = 2, pp = 1;    // produce stage/parity
  int sc = 0, cpar = 0;  // consume stage/parity
  uint32_t pF = 0;       // probe-ahead result

  for (int kt = 0; kt < KITERS; ++kt) {
    const bool produce = (kt + 2 < KITERS);
    const int nsc = (sc == 2) ? 0 : sc + 1;
    const int ncp = (nsc == 0) ? (cpar ^ 1) : cpar;

    if (!pF) MBARRIER_WAIT_PARITY(sb + 8 * sc, cpar);
    pF = 0;
    const uint32_t aBase = sb + SM_STAGE0 + sc * STAGE_BYTES;
    const uint32_t bBase = aBase + A_BYTES;

    uint32_t a[2][4][4], b[2][4][4];

    // preload ks=0 fragments into buffer 0
#pragma unroll
    for (int mt = 0; mt < 4; ++mt) {
      uint32_t off = (uint32_t)((a_row + mt * 16) * 128 + a_kb);
      LDSM_X4(a[0][mt][0], a[0][mt][1], a[0][mt][2], a[0][mt][3],
              aBase + SWZ128(off));
    }
#pragma unroll
    for (int p = 0; p < 4; ++p) {
      uint32_t off = (uint32_t)((b_row + p * 16) * 128 + b_kb);
      LDSM_X4(b[0][p][0], b[0][p][1], b[0][p][2], b[0][p][3],
              bBase + SWZ128(off));
    }

#pragma unroll
    for (int ks = 0; ks < 4; ++ks) {
      const int cb = ks & 1;
      const int nb = cb ^ 1;
      if (ks < 3) {  // prefetch ks+1 frags into the other buffer
#pragma unroll
        for (int mt = 0; mt < 4; ++mt) {
          uint32_t off =
              (uint32_t)((a_row + mt * 16) * 128 + (ks + 1) * 32 + a_kb);
          LDSM_X4(a[nb][mt][0], a[nb][mt][1], a[nb][mt][2], a[nb][mt][3],
                  aBase + SWZ128(off));
        }
#pragma unroll
        for (int p = 0; p < 4; ++p) {
          uint32_t off =
              (uint32_t)((b_row + p * 16) * 128 + (ks + 1) * 32 + b_kb);
          LDSM_X4(b[nb][p][0], b[nb][p][1], b[nb][p][2], b[nb][p][3],
                  bBase + SWZ128(off));
        }
      }
      if (ks == 1 && produce) {
        MBARRIER_WAIT_PARITY_RELAXED(sb + 24 + 8 * sp, pp);
        fill_part(sp, kt + 2, 0);
        fill_part(sp, kt + 2, 1);
      }
      if (ks == 2) {
        if (produce) {
          fill_part(sp, kt + 2, 2);
          fill_part(sp, kt + 2, 3);
          CP_ASYNC_MBAR_ARRIVE(sb + 8 * sp);  // seal produced stage
        }
        MBARRIER_ARRIVE(sb + 24 + 8 * sc);  // all LDSMs of stage issued
        MBARRIER_PROBE(pF, sb + 8 * nsc, ncp);
      }
#pragma unroll
      for (int mt = 0; mt < 4; ++mt)
#pragma unroll
        for (int nt = 0; nt < 8; ++nt)
          MMA16816(c[mt][nt][0], c[mt][nt][1], c[mt][nt][2], c[mt][nt][3],
                   a[cb][mt][0], a[cb][mt][1], a[cb][mt][2], a[cb][mt][3],
                   b[cb][nt >> 1][(nt & 1) * 2],
                   b[cb][nt >> 1][(nt & 1) * 2 + 1]);
    }

    sp = (sp == 2) ? 0 : sp + 1;
    if (sp == 0) pp ^= 1;
    sc = nsc;
    cpar = ncp;
  }

  // ------------------------------ epilogue ---------------------------------
  const int mrow = m0 + wm * 64 + (lid >> 2);
  const int ncol = n0 + wn * 64 + (lid & 3) * 2;
#pragma unroll
  for (int mt = 0; mt < 4; ++mt) {
#pragma unroll
    for (int nt = 0; nt < 8; ++nt) {
      const float2 b2 = *reinterpret_cast<const float2*>(bias + ncol + nt * 8);
      float* p0 = out + (size_t)(mrow + mt * 16) * N_TOTAL + ncol + nt * 8;
      float* p1 = p0 + 8 * N_TOTAL;
      float2 v0 = {c[mt][nt][0] + b2.x, c[mt][nt][1] + b2.y};
      float2 v1 = {c[mt][nt][2] + b2.x, c[mt][nt][3] + b2.y};
      *reinterpret_cast<float2*>(p0) = v0;
      *reinterpret_cast<float2*>(p1) = v1;
    }
  }
}

// ------------------------------- launcher ----------------------------------

extern "C" void kernel_launch(void* const* d_in, const int* in_sizes, int n_in,
                              void* d_out, int out_size) {
  const float* x = (const float*)d_in[0];
  const int* codes = (const int*)d_in[1];
  const float* scale = (const float*)d_in[2];
  const float* bias = (const float*)d_in[3];
  float* out = (float*)d_out;

  k_prep<<<PREP_BLOCKS, 256>>>((const int4*)codes, scale, (const float4*)x);

  cudaFuncSetAttribute(k_gemm, cudaFuncAttributeMaxDynamicSharedMemorySize,
                       SMEM_BYTES);
  dim3 grid(N_TOTAL / BN, M_TOTAL / BM);  // (32, 64)
  k_gemm<<<grid, 128, SMEM_BYTES>>>(bias, out);
}